// round 3
// baseline (speedup 1.0000x reference)
#include <cuda_runtime.h>
#include <math.h>

// maps: [128, 33, 224, 224] fp32  -> d_in[0]
// w1:   [100, 33]            fp32 -> d_in[1]
// w2:   [10, 100]            fp32 -> d_in[2]
// out:  x_sun [128,33] (4224 floats) then x_son stack [9,128,10] (11520 floats)

#define PLANE_ELEMS  (224 * 224)       // 50176
#define PLANE_VEC4   (PLANE_ELEMS / 4) // 12544
#define POOL_THREADS 256
#define POOL_ITERS   (PLANE_VEC4 / POOL_THREADS) // 49, exact
#define CHANNELS     33
#define BATCH        128
#define N_PLANES     (BATCH * CHANNELS) // 4224
#define X_SUN_ELEMS  (BATCH * CHANNELS) // 4224

__device__ int g_batch_counter[BATCH];   // zero-init; consumer resets each run

// ---------------------------------------------------------------------------
// Fused kernel: global average pool per (b,c) plane; the last block of each
// batch runs the MLP head for that batch inline (overlaps with pool drain).
// ---------------------------------------------------------------------------
__global__ __launch_bounds__(POOL_THREADS, 4)
void fused_kernel(const float4* __restrict__ maps,
                  const float* __restrict__ w1,
                  const float* __restrict__ w2,
                  float* __restrict__ out)
{
    const int plane = blockIdx.x;
    const int b     = plane / CHANNELS;
    const int tid   = threadIdx.x;
    const int lane  = tid & 31;
    const int wrp   = tid >> 5;

    // ---------------- pool: mean over this plane ----------------
    {
        const float4* p = maps + (size_t)plane * PLANE_VEC4;
        float s = 0.0f;
#pragma unroll
        for (int i = 0; i < POOL_ITERS; i++) {
            float4 v = p[tid + i * POOL_THREADS];
            s += (v.x + v.y) + (v.z + v.w);
        }
#pragma unroll
        for (int off = 16; off > 0; off >>= 1)
            s += __shfl_down_sync(0xFFFFFFFFu, s, off);

        __shared__ float warp_sums[POOL_THREADS / 32];
        if (lane == 0) warp_sums[wrp] = s;
        __syncthreads();
        if (tid == 0) {
            float t = 0.0f;
#pragma unroll
            for (int w = 0; w < POOL_THREADS / 32; w++) t += warp_sums[w];
            out[plane] = t * (1.0f / (float)PLANE_ELEMS);
        }
    }

    // ---------------- arrival: am I the last plane of batch b? ----------------
    __shared__ int is_last;
    if (tid == 0) {
        __threadfence();  // make out[plane] visible before the arrival tick
        int prev = atomicAdd(&g_batch_counter[b], 1);
        is_last = (prev == CHANNELS - 1);
        if (prev == CHANNELS - 1)
            g_batch_counter[b] = 0;      // reset for next graph replay
    }
    __syncthreads();
    if (!is_last) return;

    // ---------------- head for batch b (block-uniform path) ----------------
    __shared__ float t33[CHANNELS];
    __shared__ float g[100];
    __shared__ float votes[10][104];

    if (tid < CHANNELS)
        t33[tid] = tanhf(__ldcg(&out[b * CHANNELS + tid]));
    __syncthreads();

    if (tid < 100) {
        float s = 0.0f;
#pragma unroll
        for (int c = 0; c < CHANNELS; c++)
            s = fmaf(t33[c], w1[tid * CHANNELS + c], s);
        g[tid] = fmaxf(s, 0.0f);
    }
    __syncthreads();

    // 8 warps cover 10 outputs: warp w -> o=w; warps 0,1 also -> o=w+8
    const int KS[8] = {3, 4, 5, 6, 7, 10, 15, 20};
    float* son = out + X_SUN_ELEMS;

    const int n_o = (wrp < 2) ? 2 : 1;
    for (int t = 0; t < n_o; t++) {
        const int o = wrp + t * 8;

        float v0 = g[lane]      * w2[o * 100 + lane];
        float v1 = g[lane + 32] * w2[o * 100 + lane + 32];
        float v2 = g[lane + 64] * w2[o * 100 + lane + 64];
        float v3 = (lane < 4) ? g[lane + 96] * w2[o * 100 + lane + 96] : 0.0f;

        votes[o][lane]      = v0;
        votes[o][lane + 32] = v1;
        votes[o][lane + 64] = v2;
        if (lane < 4) votes[o][lane + 96] = v3;
        __syncwarp();

        int r0 = 0, r1 = 0, r2 = 0, r3 = 0;
        const int i0 = lane, i1 = lane + 32, i2 = lane + 64, i3 = lane + 96;
#pragma unroll 4
        for (int j = 0; j < 100; j++) {
            float u = votes[o][j];             // broadcast read
            r0 += (u > v0) | ((u == v0) & (j < i0));
            r1 += (u > v1) | ((u == v1) & (j < i1));
            r2 += (u > v2) | ((u == v2) & (j < i2));
            r3 += (u > v3) | ((u == v3) & (j < i3));
        }
        if (lane >= 4) r3 = 100;

        float sk[9];
#pragma unroll
        for (int k = 0; k < 8; k++) {
            float a = 0.0f;
            if (r0 < KS[k]) a += v0;
            if (r1 < KS[k]) a += v1;
            if (r2 < KS[k]) a += v2;
            if (r3 < KS[k]) a += v3;
            sk[k] = a;
        }
        sk[8] = v0 + v1 + v2 + v3;             // dense pass

#pragma unroll
        for (int k = 0; k < 9; k++) {
#pragma unroll
            for (int off = 16; off > 0; off >>= 1)
                sk[k] += __shfl_down_sync(0xFFFFFFFFu, sk[k], off);
        }

        if (lane == 0) {
#pragma unroll
            for (int k = 0; k < 9; k++)
                son[k * (BATCH * 10) + b * 10 + o] = sk[k];
        }
        __syncwarp();
    }
}

// ---------------------------------------------------------------------------
extern "C" void kernel_launch(void* const* d_in, const int* in_sizes, int n_in,
                              void* d_out, int out_size)
{
    const float4* maps = (const float4*)d_in[0];
    const float*  w1   = (const float*)d_in[1];
    const float*  w2   = (const float*)d_in[2];
    float* out = (float*)d_out;

    fused_kernel<<<N_PLANES, POOL_THREADS>>>(maps, w1, w2, out);
}

// round 4
// speedup vs baseline: 1.0556x; 1.0556x over previous
#include <cuda_runtime.h>
#include <math.h>

// maps: [128, 33, 224, 224] fp32  -> d_in[0]
// w1:   [100, 33]            fp32 -> d_in[1]
// w2:   [10, 100]            fp32 -> d_in[2]
// out:  x_sun [128,33] (4224 floats) then x_son stack [9,128,10] (11520 floats)

#define PLANE_ELEMS  (224 * 224)       // 50176
#define PLANE_VEC4   (PLANE_ELEMS / 4) // 12544
#define POOL_THREADS 256
#define POOL_ITERS   (PLANE_VEC4 / POOL_THREADS) // 49, exact
#define CHANNELS     33
#define BATCH        128
#define N_PLANES     (BATCH * CHANNELS) // 4224
#define X_SUN_ELEMS  (BATCH * CHANNELS) // 4224

__device__ int g_batch_counter[BATCH];   // zero-init; winner resets each run

// ---------------------------------------------------------------------------
// Fused kernel: global average pool per (b,c) plane; the LAST arriving block
// of each batch runs that batch's MLP head inline, overlapped with the
// remaining pool work. __launch_bounds__(256,8) pins regs<=32 so the pool
// keeps the occupancy that reached 7.3 TB/s standalone; head spills are
// confined to 128 of 4224 blocks.
// ---------------------------------------------------------------------------
__global__ __launch_bounds__(POOL_THREADS, 8)
void fused_kernel(const float4* __restrict__ maps,
                  const float* __restrict__ w1,
                  const float* __restrict__ w2,
                  float* __restrict__ out)
{
    const int plane = blockIdx.x;
    const int b     = plane / CHANNELS;
    const int tid   = threadIdx.x;
    const int lane  = tid & 31;
    const int wrp   = tid >> 5;

    // ---------------- pool: mean over this plane ----------------
    {
        const float4* p = maps + (size_t)plane * PLANE_VEC4;
        float s = 0.0f;
#pragma unroll
        for (int i = 0; i < POOL_ITERS; i++) {
            float4 v = p[tid + i * POOL_THREADS];
            s += (v.x + v.y) + (v.z + v.w);
        }
#pragma unroll
        for (int off = 16; off > 0; off >>= 1)
            s += __shfl_down_sync(0xFFFFFFFFu, s, off);

        __shared__ float warp_sums[POOL_THREADS / 32];
        if (lane == 0) warp_sums[wrp] = s;
        __syncthreads();
        if (tid == 0) {
            float t = 0.0f;
#pragma unroll
            for (int w = 0; w < POOL_THREADS / 32; w++) t += warp_sums[w];
            out[plane] = t * (1.0f / (float)PLANE_ELEMS);
        }
    }

    // ---------------- arrival: last plane of batch b? ----------------
    __shared__ int is_last;
    if (tid == 0) {
        __threadfence();  // publish out[plane] before the arrival tick
        int prev = atomicAdd(&g_batch_counter[b], 1);
        is_last = (prev == CHANNELS - 1);
        if (prev == CHANNELS - 1)
            g_batch_counter[b] = 0;      // reset for next graph replay
    }
    __syncthreads();
    if (!is_last) return;

    // ---------------- head for batch b ----------------
    __shared__ float t33[CHANNELS];
    __shared__ float g[100];
    __shared__ float votes[10][104];

    if (tid < CHANNELS)
        t33[tid] = tanhf(__ldcg(&out[b * CHANNELS + tid]));
    __syncthreads();

    if (tid < 100) {
        float s = 0.0f;
#pragma unroll
        for (int c = 0; c < CHANNELS; c++)
            s = fmaf(t33[c], w1[tid * CHANNELS + c], s);
        g[tid] = fmaxf(s, 0.0f);
    }
    __syncthreads();

    // 8 warps cover 10 outputs: warp w -> o=w; warps 0,1 also -> o=w+8
    const int KS[8] = {3, 4, 5, 6, 7, 10, 15, 20};
    float* son = out + X_SUN_ELEMS;

    const int n_o = (wrp < 2) ? 2 : 1;
    for (int t = 0; t < n_o; t++) {
        const int o = wrp + t * 8;

        float v0 = g[lane]      * w2[o * 100 + lane];
        float v1 = g[lane + 32] * w2[o * 100 + lane + 32];
        float v2 = g[lane + 64] * w2[o * 100 + lane + 64];
        float v3 = (lane < 4) ? g[lane + 96] * w2[o * 100 + lane + 96] : 0.0f;

        votes[o][lane]      = v0;
        votes[o][lane + 32] = v1;
        votes[o][lane + 64] = v2;
        if (lane < 4) votes[o][lane + 96] = v3;
        __syncwarp();

        // rank via counting (strict total order with index tie-break)
        int r0 = 0, r1 = 0, r2 = 0, r3 = 0;
        const int i0 = lane, i1 = lane + 32, i2 = lane + 64, i3 = lane + 96;
#pragma unroll 4
        for (int j = 0; j < 100; j++) {
            float u = votes[o][j];             // broadcast read
            r0 += (u > v0) | ((u == v0) & (j < i0));
            r1 += (u > v1) | ((u == v1) & (j < i1));
            r2 += (u > v2) | ((u == v2) & (j < i2));
            r3 += (u > v3) | ((u == v3) & (j < i3));
        }
        if (lane >= 4) r3 = 100;

        float sk[9];
#pragma unroll
        for (int k = 0; k < 8; k++) {
            float a = 0.0f;
            if (r0 < KS[k]) a += v0;
            if (r1 < KS[k]) a += v1;
            if (r2 < KS[k]) a += v2;
            if (r3 < KS[k]) a += v3;
            sk[k] = a;
        }
        sk[8] = v0 + v1 + v2 + v3;             // dense pass

#pragma unroll
        for (int k = 0; k < 9; k++) {
#pragma unroll
            for (int off = 16; off > 0; off >>= 1)
                sk[k] += __shfl_down_sync(0xFFFFFFFFu, sk[k], off);
        }

        if (lane == 0) {
#pragma unroll
            for (int k = 0; k < 9; k++)
                son[k * (BATCH * 10) + b * 10 + o] = sk[k];
        }
        __syncwarp();
    }
}

// ---------------------------------------------------------------------------
extern "C" void kernel_launch(void* const* d_in, const int* in_sizes, int n_in,
                              void* d_out, int out_size)
{
    const float4* maps = (const float4*)d_in[0];
    const float*  w1   = (const float*)d_in[1];
    const float*  w2   = (const float*)d_in[2];
    float* out = (float*)d_out;

    fused_kernel<<<N_PLANES, POOL_THREADS>>>(maps, w1, w2, out);
}

// round 5
// speedup vs baseline: 1.1768x; 1.1147x over previous
#include <cuda_runtime.h>
#include <math.h>

// maps: [128, 33, 224, 224] fp32  -> d_in[0]
// w1:   [100, 33]            fp32 -> d_in[1]
// w2:   [10, 100]            fp32 -> d_in[2]
// out:  x_sun [128,33] (4224 floats) then x_son stack [9,128,10] (11520 floats)

#define PLANE_ELEMS  (224 * 224)       // 50176
#define PLANE_VEC4   (PLANE_ELEMS / 4) // 12544
#define POOL_THREADS 256
#define POOL_ITERS   (PLANE_VEC4 / POOL_THREADS) // 49, exact
#define CHANNELS     33
#define BATCH        128
#define N_PLANES     (BATCH * CHANNELS) // 4224
#define X_SUN_ELEMS  (BATCH * CHANNELS) // 4224

// ---------------------------------------------------------------------------
// Kernel 1: global average pool per (b,c) plane. One block per plane.
// Identical structure to the version measured at ~7.3 TB/s (91% of HBM spec).
// ---------------------------------------------------------------------------
__global__ __launch_bounds__(POOL_THREADS, 8)
void pool_kernel(const float4* __restrict__ maps, float* __restrict__ out)
{
    const int plane = blockIdx.x;
    const float4* p = maps + (size_t)plane * PLANE_VEC4;
    const int tid = threadIdx.x;

    float s = 0.0f;
#pragma unroll
    for (int i = 0; i < POOL_ITERS; i++) {
        float4 v = __ldcs(&p[tid + i * POOL_THREADS]);   // streaming: no reuse
        s += (v.x + v.y) + (v.z + v.w);
    }

#pragma unroll
    for (int off = 16; off > 0; off >>= 1)
        s += __shfl_down_sync(0xFFFFFFFFu, s, off);

    __shared__ float warp_sums[POOL_THREADS / 32];
    const int lane = tid & 31;
    const int wid  = tid >> 5;
    if (lane == 0) warp_sums[wid] = s;
    __syncthreads();

    if (wid == 0) {
        float t = (lane < POOL_THREADS / 32) ? warp_sums[lane] : 0.0f;
#pragma unroll
        for (int off = 4; off > 0; off >>= 1)
            t += __shfl_down_sync(0xFFFFFFFFu, t, off);
        if (lane == 0)
            out[plane] = t * (1.0f / (float)PLANE_ELEMS);
    }

#if __CUDA_ARCH__ >= 900
    if (tid == 0) cudaTriggerProgrammaticLaunchCompletion();
#endif
}

// ---------------------------------------------------------------------------
// Kernel 2: MLP head. One block per (b, o) pair: 1280 blocks x 128 threads.
// Each thread owns exactly one vote -> rank loop is 100 iters x 1 compare.
// ---------------------------------------------------------------------------
__global__ __launch_bounds__(128, 8)
void head_kernel(const float* __restrict__ w1,
                 const float* __restrict__ w2,
                 float* __restrict__ out)
{
#if __CUDA_ARCH__ >= 900
    cudaGridDependencySynchronize();   // wait for pool results (PDL)
#endif
    const int b    = blockIdx.x / 10;
    const int o    = blockIdx.x % 10;
    const int tid  = threadIdx.x;
    const int lane = tid & 31;
    const int wrp  = tid >> 5;

    __shared__ float t33[CHANNELS];
    __shared__ float g[100];
    __shared__ float votes[100];
    __shared__ float wpart[4][9];

    if (tid < CHANNELS)
        t33[tid] = tanhf(out[b * CHANNELS + tid]);
    __syncthreads();

    // fc1 + relu (redundant across the 10 o-blocks of a batch; L2-served)
    if (tid < 100) {
        float s = 0.0f;
#pragma unroll
        for (int c = 0; c < CHANNELS; c++)
            s = fmaf(t33[c], w1[tid * CHANNELS + c], s);
        g[tid] = fmaxf(s, 0.0f);
    }
    __syncthreads();

    // vote for this output
    float v = 0.0f;
    if (tid < 100) {
        v = g[tid] * w2[o * 100 + tid];
        votes[tid] = v;
    }
    __syncthreads();

    // rank via counting: # strictly greater, index tie-break
    int r = 0;
    if (tid < 100) {
#pragma unroll 5
        for (int j = 0; j < 100; j++) {
            float u = votes[j];                     // smem broadcast
            r += (u > v) | ((u == v) & (j < tid));
        }
    } else {
        r = 100;                                    // owns nothing
    }

    // per-thread contributions to the 9 sums
    const int KS[8] = {3, 4, 5, 6, 7, 10, 15, 20};
    float sk[9];
#pragma unroll
    for (int k = 0; k < 8; k++)
        sk[k] = (r < KS[k]) ? v : 0.0f;
    sk[8] = v;                                      // dense pass

    // warp reduce, then cross-warp combine
#pragma unroll
    for (int k = 0; k < 9; k++) {
#pragma unroll
        for (int off = 16; off > 0; off >>= 1)
            sk[k] += __shfl_down_sync(0xFFFFFFFFu, sk[k], off);
    }
    if (lane == 0) {
#pragma unroll
        for (int k = 0; k < 9; k++)
            wpart[wrp][k] = sk[k];
    }
    __syncthreads();

    if (tid < 9) {
        float s = wpart[0][tid] + wpart[1][tid] + wpart[2][tid] + wpart[3][tid];
        out[X_SUN_ELEMS + tid * (BATCH * 10) + b * 10 + o] = s;
    }
}

// ---------------------------------------------------------------------------
extern "C" void kernel_launch(void* const* d_in, const int* in_sizes, int n_in,
                              void* d_out, int out_size)
{
    const float4* maps = (const float4*)d_in[0];
    const float*  w1   = (const float*)d_in[1];
    const float*  w2   = (const float*)d_in[2];
    float* out = (float*)d_out;

    pool_kernel<<<N_PLANES, POOL_THREADS>>>(maps, out);

    // head with programmatic dependent launch (overlap launch with pool tail)
    cudaLaunchConfig_t cfg = {};
    cfg.gridDim  = dim3(BATCH * 10, 1, 1);
    cfg.blockDim = dim3(128, 1, 1);
    cfg.dynamicSmemBytes = 0;
    cfg.stream = 0;
    cudaLaunchAttribute attr[1];
    attr[0].id = cudaLaunchAttributeProgrammaticStreamSerialization;
    attr[0].val.programmaticStreamSerializationAllowed = 1;
    cfg.attrs = attr;
    cfg.numAttrs = 1;

    cudaError_t e = cudaLaunchKernelEx(&cfg, head_kernel, w1, w2, out);
    if (e != cudaSuccess) {
        (void)cudaGetLastError();                   // clear, fall back
        head_kernel<<<BATCH * 10, 128>>>(w1, w2, out);
    }
}